// round 1
// baseline (speedup 1.0000x reference)
#include <cuda_runtime.h>
#include <math.h>

// Problem constants (fixed by the dataset)
#define NB        8          // batch
#define C_IN      4
#define N_ETYPE   5
#define N_NTYPE   7
#define C_OUT     32
#define TEMB_CH   512
#define FAN       55         // N_ETYPE * (C_IN + N_NTYPE)
#define BSTRIDE   12         // padded bucket stride (11 -> 12 floats, 48B, 16B aligned)

// Scratch: agg buckets [N * N_ETYPE, BSTRIDE] floats. Zero-initialized at module
// load; the GEMV kernel re-zeros every row it consumes, so the zero-invariant
// holds across graph replays.
__device__ float g_agg[400000 * N_ETYPE * BSTRIDE];   // 96 MB
__device__ float g_inj[NB * C_OUT];

// ---------------------------------------------------------------------------
// Kernel 1: time embedding. One block per batch element.
// temb = (swish(emb @ W1 + b1)) @ W2 + b2 ; inj = swish(temb) @ W_temb
// ---------------------------------------------------------------------------
__global__ void temb_kernel(const float* __restrict__ t,
                            const float* __restrict__ W1, const float* __restrict__ b1,
                            const float* __restrict__ W2, const float* __restrict__ b2,
                            const float* __restrict__ Wt) {
    __shared__ float emb[128];
    __shared__ float h1[512];
    __shared__ float sw2[512];
    const int b = blockIdx.x;
    const int tid = threadIdx.x;

    if (tid < 64) {
        // freqs[i] = exp(-i * ln(10000)/63)
        float f = expf(-(float)tid * (logf(10000.0f) / 63.0f));
        float ang = t[b] * f;
        emb[tid]      = sinf(ang);
        emb[tid + 64] = cosf(ang);
    }
    __syncthreads();

    // lin1 + swish
    {
        float s = b1[tid];
        #pragma unroll 8
        for (int i = 0; i < 128; i++) s += emb[i] * W1[i * 512 + tid];
        h1[tid] = s * (1.0f / (1.0f + expf(-s)));
    }
    __syncthreads();

    // lin2 (no activation) ; swish applied for the injection projection
    {
        float s = b2[tid];
        #pragma unroll 8
        for (int i = 0; i < 512; i++) s += h1[i] * W2[i * 512 + tid];
        sw2[tid] = s * (1.0f / (1.0f + expf(-s)));
    }
    __syncthreads();

    if (tid < C_OUT) {
        float s = 0.0f;
        #pragma unroll 8
        for (int i = 0; i < 512; i++) s += sw2[i] * Wt[i * C_OUT + tid];
        g_inj[b * C_OUT + tid] = s;
    }
}

// ---------------------------------------------------------------------------
// Kernel 2: edge scatter. For each edge (row <- col, etype):
//   bucket = row*5 + etype
//   agg[bucket][0:4]        += x[col]          (one red.v4.f32)
//   agg[bucket][4+nt[col]]  += 1.0             (one scalar red)
// ---------------------------------------------------------------------------
__global__ void scatter_kernel(const int* __restrict__ ei,
                               const int* __restrict__ etype,
                               const int* __restrict__ ntype,
                               const float* __restrict__ x,
                               int E) {
    int e = blockIdx.x * blockDim.x + threadIdx.x;
    if (e >= E) return;
    int row = ei[e];
    int col = ei[E + e];
    int et  = etype[e];
    int nt  = ntype[col];
    float4 xv = *reinterpret_cast<const float4*>(x + (size_t)col * C_IN);
    float* base = g_agg + ((size_t)row * N_ETYPE + et) * BSTRIDE;
    asm volatile("red.global.add.v4.f32 [%0], {%1,%2,%3,%4};"
                 :: "l"(base), "f"(xv.x), "f"(xv.y), "f"(xv.z), "f"(xv.w)
                 : "memory");
    atomicAdd(base + 4 + nt, 1.0f);
}

// ---------------------------------------------------------------------------
// Kernel 3: per-node GEMV + temb injection + agg re-zero.
//   out[n,c] = 0.2 * sum_{et,j} agg[(n*5+et)*12 + j] * W_conv[(et*11+j)*32 + c]
//              + inj[batch_id[n], c]
// ---------------------------------------------------------------------------
__global__ void gemv_kernel(const float* __restrict__ Wc,
                            const int* __restrict__ batch_id,
                            float* __restrict__ out,
                            int N) {
    __shared__ float Ws[FAN * C_OUT];          // 7040 B
    __shared__ float injs[NB * 33];            // stride 33 avoids bank conflicts
    const int tid = threadIdx.x;
    for (int i = tid; i < FAN * C_OUT; i += blockDim.x) Ws[i] = Wc[i];
    if (tid < NB * C_OUT) {
        int b = tid >> 5, c = tid & 31;
        injs[b * 33 + c] = g_inj[tid];
    }
    __syncthreads();

    int n = blockIdx.x * blockDim.x + tid;
    if (n >= N) return;

    float acc[C_OUT];
    #pragma unroll
    for (int c = 0; c < C_OUT; c++) acc[c] = 0.0f;

    float* aggp = g_agg + (size_t)n * (N_ETYPE * BSTRIDE);

    #pragma unroll
    for (int et = 0; et < N_ETYPE; et++) {
        float4 v0 = *reinterpret_cast<float4*>(aggp + et * BSTRIDE + 0);
        float4 v1 = *reinterpret_cast<float4*>(aggp + et * BSTRIDE + 4);
        float4 v2 = *reinterpret_cast<float4*>(aggp + et * BSTRIDE + 8);
        float a[11] = {v0.x, v0.y, v0.z, v0.w,
                       v1.x, v1.y, v1.z, v1.w,
                       v2.x, v2.y, v2.z};
        #pragma unroll
        for (int j = 0; j < 11; j++) {
            float av = a[j];
            const float* w = &Ws[(et * 11 + j) * C_OUT];
            #pragma unroll
            for (int c = 0; c < C_OUT; c++) acc[c] += av * w[c];
        }
    }

    int b = batch_id[n];
    const float* iv = &injs[b * 33];
    float* op = out + (size_t)n * C_OUT;
    #pragma unroll
    for (int c = 0; c < C_OUT; c += 4) {
        float4 o;
        o.x = acc[c + 0] * 0.2f + iv[c + 0];
        o.y = acc[c + 1] * 0.2f + iv[c + 1];
        o.z = acc[c + 2] * 0.2f + iv[c + 2];
        o.w = acc[c + 3] * 0.2f + iv[c + 3];
        *reinterpret_cast<float4*>(op + c) = o;
    }

    // Re-zero this node's agg rows so the next replay starts clean.
    float4 z = make_float4(0.f, 0.f, 0.f, 0.f);
    #pragma unroll
    for (int i = 0; i < N_ETYPE * BSTRIDE / 4; i++)
        reinterpret_cast<float4*>(aggp)[i] = z;
}

// ---------------------------------------------------------------------------
// Inputs (metadata order):
//  0 x [N,4] f32        1 t [8] f32          2 edge_index [2,E] i32
//  3 edge_type [E] i32  4 node_type [N] i32  5 batch_id [N] i32
//  6 W_conv [55,32] f32 7 W1 [128,512]       8 b1 [512]
//  9 W2 [512,512]      10 b2 [512]          11 W_temb [512,32]
// Output: [N,32] f32
// ---------------------------------------------------------------------------
extern "C" void kernel_launch(void* const* d_in, const int* in_sizes, int n_in,
                              void* d_out, int out_size) {
    const float* x        = (const float*)d_in[0];
    const float* t        = (const float*)d_in[1];
    const int*   ei       = (const int*)d_in[2];
    const int*   etype    = (const int*)d_in[3];
    const int*   ntype    = (const int*)d_in[4];
    const int*   batch_id = (const int*)d_in[5];
    const float* W_conv   = (const float*)d_in[6];
    const float* W1       = (const float*)d_in[7];
    const float* b1       = (const float*)d_in[8];
    const float* W2       = (const float*)d_in[9];
    const float* b2       = (const float*)d_in[10];
    const float* W_temb   = (const float*)d_in[11];
    float* out = (float*)d_out;

    const int E = in_sizes[3];
    const int N = in_sizes[4];

    temb_kernel<<<NB, 512>>>(t, W1, b1, W2, b2, W_temb);
    scatter_kernel<<<(E + 255) / 256, 256>>>(ei, etype, ntype, x, E);
    gemv_kernel<<<(N + 255) / 256, 256>>>(W_conv, batch_id, out, N);
}

// round 2
// speedup vs baseline: 1.0010x; 1.0010x over previous
#include <cuda_runtime.h>
#include <math.h>

// Problem constants (fixed by the dataset)
#define NB        8          // batch
#define C_IN      4
#define N_ETYPE   5
#define N_NTYPE   7
#define C_OUT     32
#define TEMB_CH   512
#define FAN       55         // N_ETYPE * (C_IN + N_NTYPE)
#define BSTRIDE   12         // padded bucket stride (11 -> 12 floats, 48B, 16B aligned)

// Scratch: agg buckets [N * N_ETYPE, BSTRIDE] floats. Zero-initialized at module
// load; the GEMV kernel re-zeros every row it consumes, so the zero-invariant
// holds across graph replays.
__device__ float g_agg[400000 * N_ETYPE * BSTRIDE];   // 96 MB
__device__ float g_h1[NB * TEMB_CH];
__device__ float g_sw2[NB * TEMB_CH];
__device__ float g_inj[NB * C_OUT];

// ---------------------------------------------------------------------------
// temb stage 1: sinusoidal embedding + lin1 + swish -> g_h1[b][512]
// grid = 8 (one block per batch), 512 threads (one per output col)
// ---------------------------------------------------------------------------
__global__ void temb1_kernel(const float* __restrict__ t,
                             const float* __restrict__ W1,
                             const float* __restrict__ b1) {
    __shared__ float emb[128];
    const int b = blockIdx.x;
    const int tid = threadIdx.x;

    if (tid < 64) {
        float f = expf(-(float)tid * (logf(10000.0f) / 63.0f));
        float ang = t[b] * f;
        emb[tid]      = sinf(ang);
        emb[tid + 64] = cosf(ang);
    }
    __syncthreads();

    float s = b1[tid];
    #pragma unroll 8
    for (int i = 0; i < 128; i++) s += emb[i] * W1[i * TEMB_CH + tid];
    g_h1[b * TEMB_CH + tid] = s * (1.0f / (1.0f + expf(-s)));
}

// ---------------------------------------------------------------------------
// temb stage 2: lin2 + swish -> g_sw2[b][512]
// grid = 64: blockIdx.x = b * 8 + col_tile. 64 threads; thread -> one col.
// Each block reads a 512x64 slice of W2 (coalesced per warp); the 8 batch
// replicas of each slice share L2 lines.
// ---------------------------------------------------------------------------
__global__ void temb2_kernel(const float* __restrict__ W2,
                             const float* __restrict__ b2) {
    __shared__ float h1s[TEMB_CH];
    const int b  = blockIdx.x >> 3;
    const int bo = blockIdx.x & 7;
    const int tid = threadIdx.x;
    const int c = bo * 64 + tid;

    #pragma unroll 8
    for (int i = tid; i < TEMB_CH; i += 64) h1s[i] = g_h1[b * TEMB_CH + i];
    __syncthreads();

    float s = b2[c];
    #pragma unroll 8
    for (int i = 0; i < TEMB_CH; i++) s += h1s[i] * W2[i * TEMB_CH + c];
    g_sw2[b * TEMB_CH + c] = s * (1.0f / (1.0f + expf(-s)));
}

// ---------------------------------------------------------------------------
// temb stage 3: inj = sw2 @ W_temb -> g_inj[b][32]
// grid = 8, 32 threads.
// ---------------------------------------------------------------------------
__global__ void temb3_kernel(const float* __restrict__ Wt) {
    const int b = blockIdx.x;
    const int c = threadIdx.x;
    const float* sw = g_sw2 + b * TEMB_CH;
    float s = 0.0f;
    #pragma unroll 8
    for (int i = 0; i < TEMB_CH; i++) s += sw[i] * Wt[i * C_OUT + c];
    g_inj[b * C_OUT + c] = s;
}

// ---------------------------------------------------------------------------
// Kernel 2: edge scatter. For each edge (row <- col, etype):
//   bucket = row*5 + etype
//   agg[bucket][0:4]        += x[col]          (one red.v4.f32)
//   agg[bucket][4+nt[col]]  += 1.0             (one scalar red)
// ---------------------------------------------------------------------------
__global__ void scatter_kernel(const int* __restrict__ ei,
                               const int* __restrict__ etype,
                               const int* __restrict__ ntype,
                               const float* __restrict__ x,
                               int E) {
    int e = blockIdx.x * blockDim.x + threadIdx.x;
    if (e >= E) return;
    int row = __ldg(ei + e);
    int col = __ldg(ei + E + e);
    int et  = __ldg(etype + e);
    int nt  = __ldg(ntype + col);
    float4 xv = *reinterpret_cast<const float4*>(x + (size_t)col * C_IN);
    float* base = g_agg + ((size_t)row * N_ETYPE + et) * BSTRIDE;
    asm volatile("red.global.add.v4.f32 [%0], {%1,%2,%3,%4};"
                 :: "l"(base), "f"(xv.x), "f"(xv.y), "f"(xv.z), "f"(xv.w)
                 : "memory");
    atomicAdd(base + 4 + nt, 1.0f);
}

// ---------------------------------------------------------------------------
// Kernel 3: per-node GEMV + temb injection + agg re-zero.
//   out[n,c] = 0.2 * sum_{et,j} agg[(n*5+et)*12 + j] * W_conv[(et*11+j)*32 + c]
//              + inj[batch_id[n], c]
// ---------------------------------------------------------------------------
__global__ void gemv_kernel(const float* __restrict__ Wc,
                            const int* __restrict__ batch_id,
                            float* __restrict__ out,
                            int N) {
    __shared__ float Ws[FAN * C_OUT];          // 7040 B
    __shared__ float injs[NB * 33];            // stride 33 avoids bank conflicts
    const int tid = threadIdx.x;
    for (int i = tid; i < FAN * C_OUT; i += blockDim.x) Ws[i] = Wc[i];
    if (tid < NB * C_OUT) {
        int b = tid >> 5, c = tid & 31;
        injs[b * 33 + c] = g_inj[tid];
    }
    __syncthreads();

    int n = blockIdx.x * blockDim.x + tid;
    if (n >= N) return;

    float acc[C_OUT];
    #pragma unroll
    for (int c = 0; c < C_OUT; c++) acc[c] = 0.0f;

    float* aggp = g_agg + (size_t)n * (N_ETYPE * BSTRIDE);

    #pragma unroll
    for (int et = 0; et < N_ETYPE; et++) {
        float4 v0 = *reinterpret_cast<float4*>(aggp + et * BSTRIDE + 0);
        float4 v1 = *reinterpret_cast<float4*>(aggp + et * BSTRIDE + 4);
        float4 v2 = *reinterpret_cast<float4*>(aggp + et * BSTRIDE + 8);
        float a[11] = {v0.x, v0.y, v0.z, v0.w,
                       v1.x, v1.y, v1.z, v1.w,
                       v2.x, v2.y, v2.z};
        #pragma unroll
        for (int j = 0; j < 11; j++) {
            float av = a[j];
            const float* w = &Ws[(et * 11 + j) * C_OUT];
            #pragma unroll
            for (int c = 0; c < C_OUT; c++) acc[c] += av * w[c];
        }
    }

    int b = batch_id[n];
    const float* iv = &injs[b * 33];
    float* op = out + (size_t)n * C_OUT;
    #pragma unroll
    for (int c = 0; c < C_OUT; c += 4) {
        float4 o;
        o.x = acc[c + 0] * 0.2f + iv[c + 0];
        o.y = acc[c + 1] * 0.2f + iv[c + 1];
        o.z = acc[c + 2] * 0.2f + iv[c + 2];
        o.w = acc[c + 3] * 0.2f + iv[c + 3];
        *reinterpret_cast<float4*>(op + c) = o;
    }

    // Re-zero this node's agg rows so the next replay starts clean.
    float4 z = make_float4(0.f, 0.f, 0.f, 0.f);
    #pragma unroll
    for (int i = 0; i < N_ETYPE * BSTRIDE / 4; i++)
        reinterpret_cast<float4*>(aggp)[i] = z;
}

// ---------------------------------------------------------------------------
// Inputs (metadata order):
//  0 x [N,4] f32        1 t [8] f32          2 edge_index [2,E] i32
//  3 edge_type [E] i32  4 node_type [N] i32  5 batch_id [N] i32
//  6 W_conv [55,32] f32 7 W1 [128,512]       8 b1 [512]
//  9 W2 [512,512]      10 b2 [512]          11 W_temb [512,32]
// Output: [N,32] f32
// ---------------------------------------------------------------------------
extern "C" void kernel_launch(void* const* d_in, const int* in_sizes, int n_in,
                              void* d_out, int out_size) {
    const float* x        = (const float*)d_in[0];
    const float* t        = (const float*)d_in[1];
    const int*   ei       = (const int*)d_in[2];
    const int*   etype    = (const int*)d_in[3];
    const int*   ntype    = (const int*)d_in[4];
    const int*   batch_id = (const int*)d_in[5];
    const float* W_conv   = (const float*)d_in[6];
    const float* W1       = (const float*)d_in[7];
    const float* b1       = (const float*)d_in[8];
    const float* W2       = (const float*)d_in[9];
    const float* b2       = (const float*)d_in[10];
    const float* W_temb   = (const float*)d_in[11];
    float* out = (float*)d_out;

    const int E = in_sizes[3];
    const int N = in_sizes[4];

    // Scatter first: it is independent of the temb chain and is the longest
    // pole, so the tiny temb kernels queue behind it without adding latency.
    scatter_kernel<<<(E + 255) / 256, 256>>>(ei, etype, ntype, x, E);
    temb1_kernel<<<NB, TEMB_CH>>>(t, W1, b1);
    temb2_kernel<<<NB * 8, 64>>>(W2, b2);
    temb3_kernel<<<NB, C_OUT>>>(W_temb);
    gemv_kernel<<<(N + 255) / 256, 256>>>(W_conv, batch_id, out, N);
}

// round 3
// speedup vs baseline: 1.5768x; 1.5752x over previous
#include <cuda_runtime.h>
#include <math.h>

// Problem constants (fixed by the dataset)
#define NB        8          // batch
#define C_IN      4
#define N_ETYPE   5
#define N_NTYPE   7
#define C_OUT     32
#define TEMB_CH   512
#define FAN       55         // N_ETYPE * (C_IN + N_NTYPE)
#define NMAX      400000

// Bucket layout (32 B = 8 words per (node, etype) bucket):
//   words 0..3 : float x-sums (red.add.v4.f32)
//   words 4..7 : 8 x 16-bit edge counters, fields 0..6 used (node_type one-hot)
// Zero-initialized at load; gemv re-zeros every row it consumes, so the
// zero-invariant holds across graph replays.
__device__ float g_agg[NMAX * N_ETYPE * 8];   // 64 MB
__device__ float g_h1[NB * TEMB_CH];
__device__ float g_sw2[NB * TEMB_CH];
__device__ float g_inj[NB * C_OUT];

// ---------------------------------------------------------------------------
// temb stage 1: sinusoidal embedding + lin1 + swish -> g_h1[b][512]
// grid = 8, 512 threads (one per output col, 128-long dot, coalesced W1 rows)
// ---------------------------------------------------------------------------
__global__ void temb1_kernel(const float* __restrict__ t,
                             const float* __restrict__ W1,
                             const float* __restrict__ b1) {
    __shared__ float emb[128];
    const int b = blockIdx.x;
    const int tid = threadIdx.x;

    if (tid < 64) {
        float f = expf(-(float)tid * (logf(10000.0f) / 63.0f));
        float ang = t[b] * f;
        emb[tid]      = sinf(ang);
        emb[tid + 64] = cosf(ang);
    }
    __syncthreads();

    float s = b1[tid];
    #pragma unroll 8
    for (int i = 0; i < 128; i++) s += emb[i] * W1[i * TEMB_CH + tid];
    g_h1[b * TEMB_CH + tid] = s * (1.0f / (1.0f + expf(-s)));
}

// ---------------------------------------------------------------------------
// temb stage 2: lin2 + swish -> g_sw2[b][512]
// grid = 64 (b * 8 + col_tile), 512 threads: 64 cols x 8-way K-split.
// thread (c_local = tid&63, kseg = tid>>6) sums k in [kseg*64, kseg*64+64).
// ---------------------------------------------------------------------------
__global__ void temb2_kernel(const float* __restrict__ W2,
                             const float* __restrict__ b2) {
    __shared__ float part[8][64];
    const int b  = blockIdx.x >> 3;
    const int bo = blockIdx.x & 7;
    const int cl = threadIdx.x & 63;
    const int ks = threadIdx.x >> 6;
    const int c  = bo * 64 + cl;

    const float* h1 = g_h1 + b * TEMB_CH + ks * 64;
    const float* w  = W2 + (size_t)(ks * 64) * TEMB_CH + c;
    float s = 0.0f;
    #pragma unroll 8
    for (int i = 0; i < 64; i++) s += h1[i] * w[(size_t)i * TEMB_CH];
    part[ks][cl] = s;
    __syncthreads();

    if (threadIdx.x < 64) {
        float v = b2[bo * 64 + threadIdx.x];
        #pragma unroll
        for (int k = 0; k < 8; k++) v += part[k][threadIdx.x];
        g_sw2[b * TEMB_CH + bo * 64 + threadIdx.x] = v * (1.0f / (1.0f + expf(-v)));
    }
}

// ---------------------------------------------------------------------------
// temb stage 3: inj = sw2 @ W_temb -> g_inj[b][32]
// grid = 8, 256 threads: 32 cols x 8-way K-split.
// ---------------------------------------------------------------------------
__global__ void temb3_kernel(const float* __restrict__ Wt) {
    __shared__ float part[8][33];
    const int b  = blockIdx.x;
    const int c  = threadIdx.x & 31;
    const int ks = threadIdx.x >> 5;

    const float* sw = g_sw2 + b * TEMB_CH + ks * 64;
    const float* w  = Wt + (ks * 64) * C_OUT + c;
    float s = 0.0f;
    #pragma unroll 8
    for (int i = 0; i < 64; i++) s += sw[i] * w[i * C_OUT];
    part[ks][c] = s;
    __syncthreads();

    if (threadIdx.x < 32) {
        float v = 0.0f;
        #pragma unroll
        for (int k = 0; k < 8; k++) v += part[k][threadIdx.x];
        g_inj[b * C_OUT + threadIdx.x] = v;
    }
}

// ---------------------------------------------------------------------------
// Edge scatter. For each edge (row <- col, etype):
//   bucket = row*5 + etype  (32 B)
//   bucket.x[0:4]  += x[col]                     (one red.v4.f32)
//   bucket.cnt16[nt] += 1                        (one u32 red, 16-bit field)
// ---------------------------------------------------------------------------
__global__ void scatter_kernel(const int* __restrict__ ei,
                               const int* __restrict__ etype,
                               const int* __restrict__ ntype,
                               const float* __restrict__ x,
                               int E) {
    int e = blockIdx.x * blockDim.x + threadIdx.x;
    if (e >= E) return;
    int row = __ldg(ei + e);
    int col = __ldg(ei + E + e);
    int et  = __ldg(etype + e);
    int nt  = __ldg(ntype + col);
    float4 xv = *reinterpret_cast<const float4*>(x + (size_t)col * C_IN);
    float* base = g_agg + ((size_t)row * N_ETYPE + et) * 8;
    asm volatile("red.global.add.v4.f32 [%0], {%1,%2,%3,%4};"
                 :: "l"(base), "f"(xv.x), "f"(xv.y), "f"(xv.z), "f"(xv.w)
                 : "memory");
    unsigned* cw = reinterpret_cast<unsigned*>(base) + 4 + (nt >> 1);
    atomicAdd(cw, 1u << ((nt & 1) * 16));
}

// ---------------------------------------------------------------------------
// Per-node GEMV (packed f32x2 FMA) + temb injection + agg re-zero.
//   out[n, 2k:2k+2] = sum_j a[n,j] * Ws2[j][k]  + inj[batch_id[n], 2k:2k+2]
// with Ws pre-scaled by 1/AVG_DEGREE in shared.
// ---------------------------------------------------------------------------
__global__ void gemv_kernel(const float* __restrict__ Wc,
                            const int* __restrict__ batch_id,
                            float* __restrict__ out,
                            int N) {
    __shared__ float Ws[FAN * C_OUT];          // pre-scaled by 0.2
    __shared__ float injs[NB * 33];            // stride 33 avoids bank conflicts
    const int tid = threadIdx.x;
    for (int i = tid; i < FAN * C_OUT; i += blockDim.x) Ws[i] = Wc[i] * 0.2f;
    if (tid < NB * C_OUT) {
        int b = tid >> 5, c = tid & 31;
        injs[b * 33 + c] = g_inj[tid];
    }
    __syncthreads();

    int n = blockIdx.x * blockDim.x + tid;
    if (n >= N) return;

    unsigned long long acc2[C_OUT / 2];
    #pragma unroll
    for (int k = 0; k < C_OUT / 2; k++) acc2[k] = 0ULL;

    float* aggp = g_agg + (size_t)n * (N_ETYPE * 8);
    const unsigned long long* Ws64 = reinterpret_cast<const unsigned long long*>(Ws);

    #pragma unroll
    for (int et = 0; et < N_ETYPE; et++) {
        float4 v0 = *reinterpret_cast<float4*>(aggp + et * 8);
        uint4  cw = *reinterpret_cast<uint4*>(aggp + et * 8 + 4);
        float a[11];
        a[0] = v0.x; a[1] = v0.y; a[2] = v0.z; a[3] = v0.w;
        a[4]  = (float)(cw.x & 0xFFFFu);
        a[5]  = (float)(cw.x >> 16);
        a[6]  = (float)(cw.y & 0xFFFFu);
        a[7]  = (float)(cw.y >> 16);
        a[8]  = (float)(cw.z & 0xFFFFu);
        a[9]  = (float)(cw.z >> 16);
        a[10] = (float)(cw.w & 0xFFFFu);
        #pragma unroll
        for (int j = 0; j < 11; j++) {
            unsigned long long av2;
            asm("mov.b64 %0, {%1, %1};" : "=l"(av2) : "f"(a[j]));
            const unsigned long long* w = Ws64 + (et * 11 + j) * (C_OUT / 2);
            #pragma unroll
            for (int k = 0; k < C_OUT / 2; k++) {
                asm("fma.rn.f32x2 %0, %1, %2, %0;"
                    : "+l"(acc2[k]) : "l"(av2), "l"(w[k]));
            }
        }
    }

    int b = batch_id[n];
    const float* iv = &injs[b * 33];
    float* op = out + (size_t)n * C_OUT;
    #pragma unroll
    for (int k = 0; k < C_OUT / 2; k += 2) {
        float l0, h0, l1, h1;
        asm("mov.b64 {%0, %1}, %2;" : "=f"(l0), "=f"(h0) : "l"(acc2[k]));
        asm("mov.b64 {%0, %1}, %2;" : "=f"(l1), "=f"(h1) : "l"(acc2[k + 1]));
        float4 o;
        o.x = l0 + iv[2 * k + 0];
        o.y = h0 + iv[2 * k + 1];
        o.z = l1 + iv[2 * k + 2];
        o.w = h1 + iv[2 * k + 3];
        *reinterpret_cast<float4*>(op + 2 * k) = o;
    }

    // Re-zero this node's agg buckets (40 floats) for the next replay.
    float4 z = make_float4(0.f, 0.f, 0.f, 0.f);
    #pragma unroll
    for (int i = 0; i < N_ETYPE * 2; i++)
        reinterpret_cast<float4*>(aggp)[i] = z;
}

// ---------------------------------------------------------------------------
// Inputs (metadata order):
//  0 x [N,4] f32        1 t [8] f32          2 edge_index [2,E] i32
//  3 edge_type [E] i32  4 node_type [N] i32  5 batch_id [N] i32
//  6 W_conv [55,32] f32 7 W1 [128,512]       8 b1 [512]
//  9 W2 [512,512]      10 b2 [512]          11 W_temb [512,32]
// Output: [N,32] f32
// ---------------------------------------------------------------------------
extern "C" void kernel_launch(void* const* d_in, const int* in_sizes, int n_in,
                              void* d_out, int out_size) {
    const float* x        = (const float*)d_in[0];
    const float* t        = (const float*)d_in[1];
    const int*   ei       = (const int*)d_in[2];
    const int*   etype    = (const int*)d_in[3];
    const int*   ntype    = (const int*)d_in[4];
    const int*   batch_id = (const int*)d_in[5];
    const float* W_conv   = (const float*)d_in[6];
    const float* W1       = (const float*)d_in[7];
    const float* b1       = (const float*)d_in[8];
    const float* W2       = (const float*)d_in[9];
    const float* b2       = (const float*)d_in[10];
    const float* W_temb   = (const float*)d_in[11];
    float* out = (float*)d_out;

    const int E = in_sizes[3];
    const int N = in_sizes[4];

    scatter_kernel<<<(E + 255) / 256, 256>>>(ei, etype, ntype, x, E);
    temb1_kernel<<<NB, TEMB_CH>>>(t, W1, b1);
    temb2_kernel<<<NB * 8, 512>>>(W2, b2);
    temb3_kernel<<<NB, 256>>>(W_temb);
    gemv_kernel<<<(N + 255) / 256, 256>>>(W_conv, batch_id, out, N);
}